// round 13
// baseline (speedup 1.0000x reference)
#include <cuda_runtime.h>
#include <cuda_fp16.h>
#include <math.h>

// PlanesweepCorrelation: N=2, C=64, S=32, H=128, W=160, G=8
#define NN 2
#define CC 64
#define SS 32
#define HH 128
#define WW 160
#define HWSZ (HH * WW)          // 20480
#define NPIX (NN * HWSZ)        // 40960
#define NG 8
#define CORR_ELEMS ((size_t)NN * NG * SS * HWSZ)   // 10,485,760
#define PIX_PER_BLK 16

// Normalized NHWC scratch, both fp16.
__device__ __half g_srcT[NPIX * CC];
__device__ __half g_refT[NPIX * CC];

// ---------------------------------------------------------------------------
// Prepass: L2-normalize over channels, transpose NCHW -> NHWC (fp16 out).
// ---------------------------------------------------------------------------
__global__ __launch_bounds__(256) void norm_transpose_kernel(
    const float* __restrict__ ref, const float* __restrict__ src)
{
    const bool is_src = (blockIdx.y != 0);
    const float* in  = is_src ? src : ref;
    __half*      dst = is_src ? g_srcT : g_refT;

    __shared__ float tile[32][CC + 1];
    __shared__ float inv[32];

    int tid   = threadIdx.x;
    int pbase = blockIdx.x * 32;

    {
        int pp = tid & 31;
        int cc = tid >> 5;
        int p  = pbase + pp;
        int n  = p / HWSZ;
        int hw = p - n * HWSZ;
        const float* base = in + (size_t)n * CC * HWSZ + hw;
#pragma unroll
        for (int it = 0; it < 8; it++) {
            int c = cc + it * 8;
            tile[pp][c] = base[(size_t)c * HWSZ];
        }
    }
    __syncthreads();

    {
        int pp = tid >> 3;
        int k  = tid & 7;
        float s = 0.f;
#pragma unroll
        for (int j = 0; j < 8; j++) {
            float v = tile[pp][k * 8 + j];
            s += v * v;
        }
        s += __shfl_xor_sync(0xffffffffu, s, 1);
        s += __shfl_xor_sync(0xffffffffu, s, 2);
        s += __shfl_xor_sync(0xffffffffu, s, 4);
        if (k == 0) inv[pp] = 1.0f / (sqrtf(s) + 1e-9f);
    }
    __syncthreads();

#pragma unroll
    for (int it = 0; it < 8; it++) {
        int idx = it * 256 + tid;
        int pp  = idx >> 6;
        int c   = idx & 63;
        dst[(size_t)(pbase + pp) * CC + c] =
            __float2half_rn(tile[pp][c] * inv[pp]);
    }
}

__device__ __forceinline__ __half2 u2h2(unsigned u) {
    return *reinterpret_cast<const __half2*>(&u);
}

// Blend 4 corners (fp16, mask-premultiplied weights in rec.x/rec.y),
// dot with fp32 ref, return group correlation.
__device__ __forceinline__ float blend_dot(
    int4 rec, uint4 c00, uint4 c10, uint4 c01, uint4 c11,
    float2 r0, float2 r1, float2 r2, float2 r3)
{
    const __half2 wp0 = u2h2((unsigned)rec.x);   // (w00, w10)
    const __half2 wp1 = u2h2((unsigned)rec.y);   // (w01, w11)
    const __half2 w00s = __low2half2(wp0);
    const __half2 w10s = __high2half2(wp0);
    const __half2 w01s = __low2half2(wp1);
    const __half2 w11s = __high2half2(wp1);

    __half2 a0 = __hmul2(w00s, u2h2(c00.x));
    __half2 a1 = __hmul2(w00s, u2h2(c00.y));
    __half2 a2 = __hmul2(w00s, u2h2(c00.z));
    __half2 a3 = __hmul2(w00s, u2h2(c00.w));
    a0 = __hfma2(w10s, u2h2(c10.x), a0);
    a1 = __hfma2(w10s, u2h2(c10.y), a1);
    a2 = __hfma2(w10s, u2h2(c10.z), a2);
    a3 = __hfma2(w10s, u2h2(c10.w), a3);
    a0 = __hfma2(w01s, u2h2(c01.x), a0);
    a1 = __hfma2(w01s, u2h2(c01.y), a1);
    a2 = __hfma2(w01s, u2h2(c01.z), a2);
    a3 = __hfma2(w01s, u2h2(c01.w), a3);
    a0 = __hfma2(w11s, u2h2(c11.x), a0);
    a1 = __hfma2(w11s, u2h2(c11.y), a1);
    a2 = __hfma2(w11s, u2h2(c11.z), a2);
    a3 = __hfma2(w11s, u2h2(c11.w), a3);

    float2 f0 = __half22float2(a0);
    float2 f1 = __half22float2(a1);
    float2 f2 = __half22float2(a2);
    float2 f3 = __half22float2(a3);
    return f0.x * r0.x + f0.y * r0.y
         + f1.x * r1.x + f1.y * r1.y
         + f2.x * r2.x + f2.y * r2.y
         + f3.x * r3.x + f3.y * r3.y;
}

// ---------------------------------------------------------------------------
// Main kernel. 256 threads = 8 warps; block covers 16 consecutive pixels
// (each warp handles 2). Octet layout: lane = (oct = plane sub-index, gl =
// channel group). 4 planes per warp iteration. Two corner sets (A/B) kept in
// flight in explicit registers: loads issued 2 iterations before use to
// cover the ~250-380cyc L2 gather latency.
// ---------------------------------------------------------------------------
__global__ void __launch_bounds__(256, 3) corr_kernel(
    const float* __restrict__ grids, float* __restrict__ out)
{
    __shared__ float s_g[2 * SS][PIX_PER_BLK + 1];   // staged grids
    __shared__ int4  s_t[PIX_PER_BLK][SS];           // {w2lo, w2hi, off, dxdy}
    __shared__ float s_c[PIX_PER_BLK][SS * NG + 1];  // corr staging
    __shared__ float s_m[PIX_PER_BLK][SS + 1];       // masks

    const int t    = threadIdx.x;
    const int w    = t >> 5;
    const int lane = t & 31;
    const int oct  = lane >> 3;      // 0..3: plane sub-index
    const int gl   = lane & 7;       // 0..7: channel group

    const int blkpix = blockIdx.x * PIX_PER_BLK;
    const int n      = blkpix / HWSZ;      // HWSZ % 16 == 0: no straddle
    const int hw0    = blkpix - n * HWSZ;

    // ---- cooperative grid staging (coalesced) ----
    const float* gb_n = grids + (size_t)n * (2 * SS) * HWSZ;
#pragma unroll
    for (int it = 0; it < 4; it++) {
        int idx = it * 256 + t;          // 0..1023
        int sc  = idx >> 4;
        int pp  = idx & 15;
        s_g[sc][pp] = gb_n[(size_t)sc * HWSZ + hw0 + pp];
    }
    __syncthreads();

    const char* sb = (const char*)(g_srcT + (size_t)n * HWSZ * CC) + gl * 16;

#pragma unroll
    for (int pi = 0; pi < 2; pi++) {
        const int p  = w * 2 + pi;
        const int hw = hw0 + p;

        // ---- prologue: lane s computes plane-s table ----
        {
            const float gx = s_g[2 * lane][p];
            const float gy = s_g[2 * lane + 1][p];
            float ixf = gx - 0.5f, iyf = gy - 0.5f;
            float x0f = floorf(ixf), y0f = floorf(iyf);
            int   x0 = (int)x0f,   y0 = (int)y0f;
            float wx1 = ixf - x0f, wy1 = iyf - y0f;
            float wx0 = 1.f - wx1, wy0 = 1.f - wy1;
            bool vx0 = (x0 >= 0)  && (x0 <  WW);
            bool vx1 = (x0 >= -1) && (x0 <  WW - 1);
            bool vy0 = (y0 >= 0)  && (y0 <  HH);
            bool vy1 = (y0 >= -1) && (y0 <  HH - 1);
            float w00 = (vx0 && vy0) ? wx0 * wy0 : 0.f;
            float w10 = (vx1 && vy0) ? wx1 * wy0 : 0.f;
            float w01 = (vx0 && vy1) ? wx0 * wy1 : 0.f;
            float w11 = (vx1 && vy1) ? wx1 * wy1 : 0.f;
            float msum = w00 + w10 + w01 + w11;
            float mask = (msum < 0.9999f) ? 0.f : 1.f;
            int xc0 = min(max(x0, 0),     WW - 1);
            int xc1 = min(max(x0 + 1, 0), WW - 1);
            int yc0 = min(max(y0, 0),     HH - 1);
            int yc1 = min(max(y0 + 1, 0), HH - 1);
            int off = (yc0 * WW + xc0) * (CC * 2);   // bytes: fp16 row = 128B
            int dx  = (xc1 - xc0) * (CC * 2);        // 0 or 128
            int dy  = (yc1 - yc0) * (WW * CC * 2);   // 0 or 20480
            __half2 wlo = __floats2half2_rn(w00 * mask, w10 * mask);
            __half2 whi = __floats2half2_rn(w01 * mask, w11 * mask);
            int4 rec;
            rec.x = *reinterpret_cast<const int*>(&wlo);
            rec.y = *reinterpret_cast<const int*>(&whi);
            rec.z = off;
            rec.w = dx | (dy << 16);
            s_t[p][lane] = rec;
            s_m[p][lane] = mask;
        }
        __syncwarp();

        // ref channels for group gl: 8 fp16 = one uint4
        const uint4 rr = *(const uint4*)(
            (const char*)g_refT + ((size_t)(n * HWSZ + hw) * CC + gl * 8) * 2);
        const float2 r0 = __half22float2(u2h2(rr.x));
        const float2 r1 = __half22float2(u2h2(rr.y));
        const float2 r2 = __half22float2(u2h2(rr.z));
        const float2 r3 = __half22float2(u2h2(rr.w));

        float* scp = s_c[p];

        // ---- distance-2 pipelined loop, explicit A/B register slots ----
        int4 recA = s_t[p][oct];             // planes k = 0,2,4,6
        int4 recB = s_t[p][4 + oct];         // planes k = 1,3,5,7
        uint4 A00, A10, A01, A11, B00, B10, B01, B11;
        {
            const int dxa = recA.w & 0xffff, dya = recA.w >> 16;
            const char* aa = sb + recA.z;
            A00 = *(const uint4*)(aa);
            A10 = *(const uint4*)(aa + dxa);
            A01 = *(const uint4*)(aa + dya);
            A11 = *(const uint4*)(aa + dxa + dya);
            const int dxb = recB.w & 0xffff, dyb = recB.w >> 16;
            const char* ab = sb + recB.z;
            B00 = *(const uint4*)(ab);
            B10 = *(const uint4*)(ab + dxb);
            B01 = *(const uint4*)(ab + dyb);
            B11 = *(const uint4*)(ab + dxb + dyb);
        }

#pragma unroll
        for (int it2 = 0; it2 < 4; it2++) {
            const int k = it2 * 2;           // even iteration index 0,2,4,6

            // --- consume A (plane set k), then refill A from k+2 ---
            {
                const int4  cur = recA;
                const uint4 c00 = A00, c10 = A10, c01 = A01, c11 = A11;
                if (it2 < 3) {
                    recA = s_t[p][((k + 2) << 2) + oct];
                    const int ndx = recA.w & 0xffff, ndy = recA.w >> 16;
                    const char* na = sb + recA.z;
                    A00 = *(const uint4*)(na);
                    A10 = *(const uint4*)(na + ndx);
                    A01 = *(const uint4*)(na + ndy);
                    A11 = *(const uint4*)(na + ndx + ndy);
                }
                float sum = blend_dot(cur, c00, c10, c01, c11, r0, r1, r2, r3);
                scp[(((k << 2) + oct) << 3) + gl] = sum;
            }

            // --- consume B (plane set k+1), then refill B from k+3 ---
            {
                const int4  cur = recB;
                const uint4 c00 = B00, c10 = B10, c01 = B01, c11 = B11;
                if (it2 < 3) {
                    recB = s_t[p][((k + 3) << 2) + oct];
                    const int ndx = recB.w & 0xffff, ndy = recB.w >> 16;
                    const char* nb = sb + recB.z;
                    B00 = *(const uint4*)(nb);
                    B10 = *(const uint4*)(nb + ndx);
                    B01 = *(const uint4*)(nb + ndy);
                    B11 = *(const uint4*)(nb + ndx + ndy);
                }
                float sum = blend_dot(cur, c00, c10, c01, c11, r0, r1, r2, r3);
                scp[((((k + 1) << 2) + oct) << 3) + gl] = sum;
            }
        }
        __syncwarp();
    }
    __syncthreads();

    // ---- store phase: coalesced from smem staging ----
    {
        const int pl = t & 15;           // pixel
        const int h  = t >> 4;           // 0..15
        float* po = out + (size_t)n * 256 * HWSZ + hw0 + pl;
#pragma unroll
        for (int i = 0; i < 16; i++) {
            int gs = i * 16 + h;         // gs = g*32 + s
            int s  = gs & 31;
            int g  = gs >> 5;
            po[(size_t)gs * HWSZ] = s_c[pl][s * 8 + g];
        }
        float* pm = out + CORR_ELEMS + (size_t)n * SS * HWSZ + hw0 + pl;
#pragma unroll
        for (int i = 0; i < 2; i++) {
            int s = i * 16 + h;
            pm[(size_t)s * HWSZ] = s_m[pl][s];
        }
    }
}

extern "C" void kernel_launch(void* const* d_in, const int* in_sizes, int n_in,
                              void* d_out, int out_size)
{
    const float* feat_ref = (const float*)d_in[0];
    const float* feat_src = (const float*)d_in[1];
    const float* grids    = (const float*)d_in[2];
    (void)in_sizes; (void)n_in; (void)out_size;

    dim3 pre_grid(NPIX / 32, 2);
    norm_transpose_kernel<<<pre_grid, 256>>>(feat_ref, feat_src);

    corr_kernel<<<NPIX / PIX_PER_BLK, 256>>>(grids, (float*)d_out);
}

// round 14
// speedup vs baseline: 1.0671x; 1.0671x over previous
#include <cuda_runtime.h>
#include <cuda_fp16.h>
#include <math.h>

// PlanesweepCorrelation: N=2, C=64, S=32, H=128, W=160, G=8
#define NN 2
#define CC 64
#define SS 32
#define HH 128
#define WW 160
#define HWSZ (HH * WW)          // 20480
#define NPIX (NN * HWSZ)        // 40960
#define NG 8
#define CORR_ELEMS ((size_t)NN * NG * SS * HWSZ)   // 10,485,760
#define PIX_PER_BLK 32

// Dynamic smem layout (bytes):
//   s_t : int4 [32][32]        = 16384   @ 0
//   s_c : float[32][257]       = 32896   @ 16384
//   s_g : float[64][33]        = 8448    @ 49280
//   s_m : float[32][33]        = 4224    @ 57728
#define SMEM_T_OFF 0
#define SMEM_C_OFF 16384
#define SMEM_G_OFF 49280
#define SMEM_M_OFF 57728
#define SMEM_TOTAL 61952

// Normalized NHWC scratch, both fp16.
__device__ __half g_srcT[NPIX * CC];
__device__ __half g_refT[NPIX * CC];

// ---------------------------------------------------------------------------
// Prepass: L2-normalize over channels, transpose NCHW -> NHWC (fp16 out).
// Phase-3 writes half2 (128B per warp-instruction).
// ---------------------------------------------------------------------------
__global__ __launch_bounds__(256) void norm_transpose_kernel(
    const float* __restrict__ ref, const float* __restrict__ src)
{
    const bool is_src = (blockIdx.y != 0);
    const float* in  = is_src ? src : ref;
    __half2*     dst = is_src ? (__half2*)g_srcT : (__half2*)g_refT;

    __shared__ float tile[32][CC + 1];
    __shared__ float inv[32];

    int tid   = threadIdx.x;
    int pbase = blockIdx.x * 32;

    {
        int pp = tid & 31;
        int cc = tid >> 5;
        int p  = pbase + pp;
        int n  = p / HWSZ;
        int hw = p - n * HWSZ;
        const float* base = in + (size_t)n * CC * HWSZ + hw;
#pragma unroll
        for (int it = 0; it < 8; it++) {
            int c = cc + it * 8;
            tile[pp][c] = base[(size_t)c * HWSZ];
        }
    }
    __syncthreads();

    {
        int pp = tid >> 3;
        int k  = tid & 7;
        float s = 0.f;
#pragma unroll
        for (int j = 0; j < 8; j++) {
            float v = tile[pp][k * 8 + j];
            s += v * v;
        }
        s += __shfl_xor_sync(0xffffffffu, s, 1);
        s += __shfl_xor_sync(0xffffffffu, s, 2);
        s += __shfl_xor_sync(0xffffffffu, s, 4);
        if (k == 0) inv[pp] = 1.0f / (sqrtf(s) + 1e-9f);
    }
    __syncthreads();

    // NHWC write, half2-vectorized: 32 px * 32 half2 = 1024 / 256 thr = 4 it
#pragma unroll
    for (int it = 0; it < 4; it++) {
        int idx = it * 256 + tid;        // 0..1023
        int pp  = idx >> 5;              // pixel 0..31
        int c2  = idx & 31;              // half2 index 0..31
        float iv = inv[pp];
        float a = tile[pp][c2 * 2]     * iv;
        float b = tile[pp][c2 * 2 + 1] * iv;
        dst[(size_t)(pbase + pp) * 32 + c2] = __floats2half2_rn(a, b);
    }
}

__device__ __forceinline__ __half2 u2h2(unsigned u) {
    return *reinterpret_cast<const __half2*>(&u);
}

// ---------------------------------------------------------------------------
// Main kernel (identical to the proven R10 design). 512 threads = 16 warps;
// block covers 32 consecutive pixels (each warp handles 2). Octet layout:
// lane = (oct = plane sub-index, gl = channel group). 4 planes per warp
// iteration; corner loads double-buffered (distance-1). Store phase writes
// 128B runs. Dynamic smem.
// ---------------------------------------------------------------------------
__global__ void __launch_bounds__(512, 2) corr_kernel(
    const float* __restrict__ grids, float* __restrict__ out)
{
    extern __shared__ char smem_raw[];
    int4  (*s_t)[SS]               = (int4 (*)[SS])(smem_raw + SMEM_T_OFF);
    float (*s_c)[SS * NG + 1]      = (float (*)[SS * NG + 1])(smem_raw + SMEM_C_OFF);
    float (*s_g)[PIX_PER_BLK + 1]  = (float (*)[PIX_PER_BLK + 1])(smem_raw + SMEM_G_OFF);
    float (*s_m)[SS + 1]           = (float (*)[SS + 1])(smem_raw + SMEM_M_OFF);

    const int t    = threadIdx.x;
    const int w    = t >> 5;         // 0..15
    const int lane = t & 31;
    const int oct  = lane >> 3;      // 0..3: plane sub-index
    const int gl   = lane & 7;       // 0..7: channel group

    const int blkpix = blockIdx.x * PIX_PER_BLK;
    const int n      = blkpix / HWSZ;      // HWSZ % 32 == 0: no straddle
    const int hw0    = blkpix - n * HWSZ;

    // ---- cooperative grid staging (coalesced) ----
    const float* gb_n = grids + (size_t)n * (2 * SS) * HWSZ;
#pragma unroll
    for (int it = 0; it < 4; it++) {
        int idx = it * 512 + t;          // 0..2047
        int sc  = idx >> 5;
        int pp  = idx & 31;
        s_g[sc][pp] = gb_n[(size_t)sc * HWSZ + hw0 + pp];
    }
    __syncthreads();

    const char* sb = (const char*)(g_srcT + (size_t)n * HWSZ * CC) + gl * 16;

#pragma unroll
    for (int pi = 0; pi < 2; pi++) {
        const int p  = w * 2 + pi;       // 0..31
        const int hw = hw0 + p;

        // ---- prologue: lane s computes plane-s table ----
        {
            const float gx = s_g[2 * lane][p];
            const float gy = s_g[2 * lane + 1][p];
            float ixf = gx - 0.5f, iyf = gy - 0.5f;
            float x0f = floorf(ixf), y0f = floorf(iyf);
            int   x0 = (int)x0f,   y0 = (int)y0f;
            float wx1 = ixf - x0f, wy1 = iyf - y0f;
            float wx0 = 1.f - wx1, wy0 = 1.f - wy1;
            bool vx0 = (x0 >= 0)  && (x0 <  WW);
            bool vx1 = (x0 >= -1) && (x0 <  WW - 1);
            bool vy0 = (y0 >= 0)  && (y0 <  HH);
            bool vy1 = (y0 >= -1) && (y0 <  HH - 1);
            float w00 = (vx0 && vy0) ? wx0 * wy0 : 0.f;
            float w10 = (vx1 && vy0) ? wx1 * wy0 : 0.f;
            float w01 = (vx0 && vy1) ? wx0 * wy1 : 0.f;
            float w11 = (vx1 && vy1) ? wx1 * wy1 : 0.f;
            float msum = w00 + w10 + w01 + w11;
            float mask = (msum < 0.9999f) ? 0.f : 1.f;
            int xc0 = min(max(x0, 0),     WW - 1);
            int xc1 = min(max(x0 + 1, 0), WW - 1);
            int yc0 = min(max(y0, 0),     HH - 1);
            int yc1 = min(max(y0 + 1, 0), HH - 1);
            int off = (yc0 * WW + xc0) * (CC * 2);   // bytes: fp16 row = 128B
            int dx  = (xc1 - xc0) * (CC * 2);        // 0 or 128
            int dy  = (yc1 - yc0) * (WW * CC * 2);   // 0 or 20480
            __half2 wlo = __floats2half2_rn(w00 * mask, w10 * mask);
            __half2 whi = __floats2half2_rn(w01 * mask, w11 * mask);
            int4 rec;
            rec.x = *reinterpret_cast<const int*>(&wlo);
            rec.y = *reinterpret_cast<const int*>(&whi);
            rec.z = off;
            rec.w = dx | (dy << 16);
            s_t[p][lane] = rec;
            s_m[p][lane] = mask;
        }
        __syncwarp();

        // ref channels for group gl: 8 fp16 = one uint4 (same line all octets)
        const uint4 rr = *(const uint4*)(
            (const char*)g_refT + ((size_t)(n * HWSZ + hw) * CC + gl * 8) * 2);
        const float2 r0 = __half22float2(u2h2(rr.x));
        const float2 r1 = __half22float2(u2h2(rr.y));
        const float2 r2 = __half22float2(u2h2(rr.z));
        const float2 r3 = __half22float2(u2h2(rr.w));

        float* scp = s_c[p];

        // ---- software-pipelined main loop: 4 planes/iter ----
        int4 rec = s_t[p][oct];
        {
            const int dx = rec.w & 0xffff;
            const int dy = rec.w >> 16;
            const char* a = sb + rec.z;
            uint4 c00 = *(const uint4*)(a);
            uint4 c10 = *(const uint4*)(a + dx);
            uint4 c01 = *(const uint4*)(a + dy);
            uint4 c11 = *(const uint4*)(a + dx + dy);

#pragma unroll
            for (int it = 0; it < 8; it++) {
                const int4 cur = rec;
                const uint4 b00 = c00, b10 = c10, b01 = c01, b11 = c11;

                if (it < 7) {                        // compile-time guard
                    rec = s_t[p][((it + 1) << 2) + oct];
                    const int ndx = rec.w & 0xffff;
                    const int ndy = rec.w >> 16;
                    const char* na = sb + rec.z;
                    c00 = *(const uint4*)(na);
                    c10 = *(const uint4*)(na + ndx);
                    c01 = *(const uint4*)(na + ndy);
                    c11 = *(const uint4*)(na + ndx + ndy);
                }

                const __half2 wp0 = u2h2((unsigned)cur.x);   // (w00, w10)
                const __half2 wp1 = u2h2((unsigned)cur.y);   // (w01, w11)
                const __half2 w00s = __low2half2(wp0);
                const __half2 w10s = __high2half2(wp0);
                const __half2 w01s = __low2half2(wp1);
                const __half2 w11s = __high2half2(wp1);

                // fp16 bilinear blend (mask folded into weights)
                __half2 a0 = __hmul2(w00s, u2h2(b00.x));
                __half2 a1 = __hmul2(w00s, u2h2(b00.y));
                __half2 a2 = __hmul2(w00s, u2h2(b00.z));
                __half2 a3 = __hmul2(w00s, u2h2(b00.w));
                a0 = __hfma2(w10s, u2h2(b10.x), a0);
                a1 = __hfma2(w10s, u2h2(b10.y), a1);
                a2 = __hfma2(w10s, u2h2(b10.z), a2);
                a3 = __hfma2(w10s, u2h2(b10.w), a3);
                a0 = __hfma2(w01s, u2h2(b01.x), a0);
                a1 = __hfma2(w01s, u2h2(b01.y), a1);
                a2 = __hfma2(w01s, u2h2(b01.z), a2);
                a3 = __hfma2(w01s, u2h2(b01.w), a3);
                a0 = __hfma2(w11s, u2h2(b11.x), a0);
                a1 = __hfma2(w11s, u2h2(b11.y), a1);
                a2 = __hfma2(w11s, u2h2(b11.z), a2);
                a3 = __hfma2(w11s, u2h2(b11.w), a3);

                // convert blended pairs, dot with fp32-converted ref
                float2 f0 = __half22float2(a0);
                float2 f1 = __half22float2(a1);
                float2 f2 = __half22float2(a2);
                float2 f3 = __half22float2(a3);
                float sum = f0.x * r0.x + f0.y * r0.y
                          + f1.x * r1.x + f1.y * r1.y
                          + f2.x * r2.x + f2.y * r2.y
                          + f3.x * r3.x + f3.y * r3.y;

                scp[(((it << 2) + oct) << 3) + gl] = sum;   // 128B run: 1 wf
            }
        }
        __syncwarp();
    }
    __syncthreads();

    // ---- store phase: 128B contiguous runs per warp-instr ----
    {
        const int pl = t & 31;           // pixel 0..31
        const int h  = t >> 5;           // 0..15
        float* po = out + (size_t)n * 256 * HWSZ + hw0 + pl;
#pragma unroll
        for (int i = 0; i < 16; i++) {
            int gs = i * 16 + h;         // gs = g*32 + s
            int s  = gs & 31;
            int g  = gs >> 5;
            po[(size_t)gs * HWSZ] = s_c[pl][s * 8 + g];
        }
        float* pm = out + CORR_ELEMS + (size_t)n * SS * HWSZ + hw0 + pl;
#pragma unroll
        for (int i = 0; i < 2; i++) {
            int s = i * 16 + h;
            pm[(size_t)s * HWSZ] = s_m[pl][s];
        }
    }
}

extern "C" void kernel_launch(void* const* d_in, const int* in_sizes, int n_in,
                              void* d_out, int out_size)
{
    const float* feat_ref = (const float*)d_in[0];
    const float* feat_src = (const float*)d_in[1];
    const float* grids    = (const float*)d_in[2];
    (void)in_sizes; (void)n_in; (void)out_size;

    // Raise dynamic-smem cap (host-side, immediate, idempotent; not a stream
    // op, so safe under graph capture).
    cudaFuncSetAttribute(corr_kernel,
                         cudaFuncAttributeMaxDynamicSharedMemorySize,
                         SMEM_TOTAL);

    dim3 pre_grid(NPIX / 32, 2);
    norm_transpose_kernel<<<pre_grid, 256>>>(feat_ref, feat_src);

    corr_kernel<<<NPIX / PIX_PER_BLK, 512, SMEM_TOTAL>>>(grids, (float*)d_out);
}